// round 15
// baseline (speedup 1.0000x reference)
#include <cuda_runtime.h>

#define BB 2
#define NN 1024
#define DD 3
#define F1 32
#define F2 64
#define NTH 512
#define NB 256

// Scratch (no allocs allowed). g_h1 feature-major: [batch][feature][point]
__device__ float g_h1[BB*F1*NN];

// ---------------------------------------------------------------------------
// Rank-query engine (validated R5/R13): cnt/sum of {c_j > q} via 256-bin
// counting histogram + bucket scan. Ties contribute a + c == 0 -> free.
// ---------------------------------------------------------------------------
struct RankSmem {
    int   cnt[NB];
    int   cur[NB];
    float bsum[NB];
    int   E[NB+1];
    float SS[NB+1];
    float sc[NN];
    float redA[16];
    float redB[16];
};

__device__ void rank_build(RankSmem* S, float c0, float c1,
                           int t, float& mn_out, float& invw_out)
{
    int lane = t & 31, w = t >> 5;

    if (t < NB) { S->cnt[t] = 0; S->bsum[t] = 0.0f; }

    // block min/max of c
    float mnl = fminf(c0, c1), mxl = fmaxf(c0, c1);
#pragma unroll
    for (int o = 16; o > 0; o >>= 1) {
        mnl = fminf(mnl, __shfl_xor_sync(0xffffffffu, mnl, o));
        mxl = fmaxf(mxl, __shfl_xor_sync(0xffffffffu, mxl, o));
    }
    if (lane == 0) { S->redA[w] = mnl; S->redB[w] = mxl; }
    __syncthreads();
    if (t < 16) {
        mnl = S->redA[t]; mxl = S->redB[t];
#pragma unroll
        for (int o = 8; o > 0; o >>= 1) {
            mnl = fminf(mnl, __shfl_xor_sync(0x0000ffffu, mnl, o));
            mxl = fmaxf(mxl, __shfl_xor_sync(0x0000ffffu, mxl, o));
        }
        if (t == 0) { S->redA[0] = mnl; S->redB[0] = (float)NB / fmaxf(mxl - mnl, 1e-30f); }
    }
    __syncthreads();
    float mn = S->redA[0], invw = S->redB[0];
    mn_out = mn; invw_out = invw;

    int b0 = min(max((int)((c0 - mn) * invw), 0), NB-1);
    int b1 = min(max((int)((c1 - mn) * invw), 0), NB-1);
    atomicAdd(&S->cnt[b0], 1);  atomicAdd(&S->bsum[b0], c0);
    atomicAdd(&S->cnt[b1], 1);  atomicAdd(&S->bsum[b1], c1);
    __syncthreads();

    // exclusive scan over NB bins (count + sum), warps 0..7
    int v = 0; float s = 0.0f;
    int vi = 0; float si = 0.0f;
    if (t < NB) {
        v = S->cnt[t]; s = S->bsum[t];
        vi = v; si = s;
#pragma unroll
        for (int o = 1; o < 32; o <<= 1) {
            int   nv = __shfl_up_sync(0xffffffffu, vi, o);
            float ns = __shfl_up_sync(0xffffffffu, si, o);
            if (lane >= o) { vi += nv; si += ns; }
        }
        if (lane == 31) { S->redA[w] = (float)vi; S->redB[w] = si; }
    }
    __syncthreads();
    if (t < 8) {
        float v8 = S->redA[t], s8 = S->redB[t];
        float vv = v8, ss = s8;
#pragma unroll
        for (int o = 1; o < 8; o <<= 1) {
            float nv = __shfl_up_sync(0x000000ffu, vv, o);
            float ns = __shfl_up_sync(0x000000ffu, ss, o);
            if (t >= o) { vv += nv; ss += ns; }
        }
        S->redA[t] = vv - v8;
        S->redB[t] = ss - s8;
    }
    __syncthreads();
    if (t < NB) {
        int   excl  = vi - v + (int)S->redA[w];
        float exclS = si - s + S->redB[w];
        S->E[t] = excl; S->SS[t] = exclS; S->cur[t] = excl;
        if (t == NB-1) { S->E[NB] = excl + v; S->SS[NB] = exclS + s; }
    }
    __syncthreads();

    int p0 = atomicAdd(&S->cur[b0], 1);  S->sc[p0] = c0;
    int p1 = atomicAdd(&S->cur[b1], 1);  S->sc[p1] = c1;
    __syncthreads();
}

__device__ __forceinline__ float rank_query(const RankSmem* S, float a, float cself,
                                            float mn, float invw)
{
    const float scale = 1.0f / (float)(NN - 1);
    float q = -a;
    int qb = min(max((int)((q - mn) * invw), 0), NB-1);
    int beg = S->E[qb], end = S->E[qb+1];
    float cnt = (float)(NN - end);
    float sum = S->SS[NB] - S->SS[qb+1];
    for (int k = beg; k < end; k++) {
        float v = S->sc[k];
        if (v > q) { cnt += 1.0f; sum += v; }
    }
    float self = fmaxf(a + cself, 0.0f);
    return (a * cnt + sum - self) * scale;
}

// ---------------------------------------------------------------------------
// Stage 1 (identical to R13): one block per (batch, feature f of 32).
// Thread t owns points (t, t+512). Writes h1 column. Also zeroes out.
// ---------------------------------------------------------------------------
__global__ __launch_bounds__(NTH) void stage1(
    const float* __restrict__ x,
    const float* __restrict__ W1,
    const float* __restrict__ b1,
    float* __restrict__ out)
{
    __shared__ RankSmem S;

    int t = threadIdx.x;

    // zero output (64 blocks x 512 threads >= 6144 elements)
    int zi = blockIdx.x * NTH + t;
    if (zi < BB*NN*DD) out[zi] = 0.0f;

    int b = blockIdx.x >> 5;
    int f = blockIdx.x & 31;

    float w0 = W1[0*F1+f], w1 = W1[1*F1+f], w2 = W1[2*F1+f];
    float w3 = W1[3*F1+f], w4 = W1[4*F1+f], w5 = W1[5*F1+f];
    float bias = b1[f];
    const float* xb = x + b*NN*DD;

    float a0, a1, c0, c1;
    {
        float x0 = xb[3*t+0], x1 = xb[3*t+1], x2 = xb[3*t+2];
        a0 = x0*w0 + x1*w1 + x2*w2 + bias;
        c0 = x0*w3 + x1*w4 + x2*w5;
        int p = t + 512;
        x0 = xb[3*p+0]; x1 = xb[3*p+1]; x2 = xb[3*p+2];
        a1 = x0*w0 + x1*w1 + x2*w2 + bias;
        c1 = x0*w3 + x1*w4 + x2*w5;
    }

    float mn, invw;
    rank_build(&S, c0, c1, t, mn, invw);

    float* hout = g_h1 + (b*F1 + f)*NN;
    hout[t]       = rank_query(&S, a0, c0, mn, invw);
    hout[t + 512] = rank_query(&S, a1, c1, mn, invw);
}

// ---------------------------------------------------------------------------
// Stage 2 (fused with block-3 closed form): one block per (batch, f2 of 64).
// CHANGE vs R13: thread t owns ADJACENT points (2t, 2t+1) -> h1 loads become
// float2 (64 LDG instead of 128), scalar FMA (no f32x2), epilogue atomics hit
// 6 consecutive floats. rank engine is mapping-invariant.
//   out[i,d] += h2[i]*(Wt[f2,d] - Wb[f2,d]*inv) + Hsum*Wb[f2,d]*inv + b3[d]/F2
// ---------------------------------------------------------------------------
__global__ __launch_bounds__(NTH) void stage2_fused(
    const float* __restrict__ W2,
    const float* __restrict__ b2,
    const float* __restrict__ W3,
    const float* __restrict__ b3,
    float* __restrict__ out)
{
    __shared__ RankSmem S;
    __shared__ float wt[F1], wb[F1];

    int t = threadIdx.x;
    int b = blockIdx.x >> 6;
    int f2 = blockIdx.x & 63;

    if (t < F1) {
        wt[t] = W2[t*F2 + f2];
        wb[t] = W2[(F1 + t)*F2 + f2];
    }
    float bias = b2[f2];
    __syncthreads();

    // projection for adjacent point pair (2t, 2t+1): float2 loads
    const float2* h1b2 = (const float2*)(g_h1 + b*F1*NN);
    float a0 = bias, c0 = 0.0f, a1 = bias, c1 = 0.0f;
#pragma unroll
    for (int f = 0; f < F1; f++) {
        float2 hv = __ldg(&h1b2[f*(NN/2) + t]);    // cross-kernel data: safe
        a0 += hv.x * wt[f];  c0 += hv.x * wb[f];
        a1 += hv.y * wt[f];  c1 += hv.y * wb[f];
    }

    float mn, invw;
    rank_build(&S, c0, c1, t, mn, invw);

    float h0 = rank_query(&S, a0, c0, mn, invw);
    float h1 = rank_query(&S, a1, c1, mn, invw);

    // block-reduce Hsum = sum_i h2[i]
    float hloc = h0 + h1;
    __syncthreads();
    int lane = t & 31, w = t >> 5;
#pragma unroll
    for (int o = 16; o > 0; o >>= 1)
        hloc += __shfl_xor_sync(0xffffffffu, hloc, o);
    if (lane == 0) S.redA[w] = hloc;
    __syncthreads();
    if (t < 16) {
        float v = S.redA[t];
#pragma unroll
        for (int o = 8; o > 0; o >>= 1)
            v += __shfl_xor_sync(0x0000ffffu, v, o);
        if (t == 0) S.redA[0] = v;
    }
    __syncthreads();
    float Hsum = S.redA[0];

    // direct output commit (F2=64 blocks contribute per output point)
    const float inv = 1.0f / (float)(NN - 1);
    float coef[DD], addc[DD];
#pragma unroll
    for (int d = 0; d < DD; d++) {
        float wtd = W3[f2*DD + d];
        float wbd = W3[(F2 + f2)*DD + d];
        coef[d] = wtd - wbd*inv;
        addc[d] = Hsum*wbd*inv + b3[d]*(1.0f/(float)F2);
    }
    float* o0 = out + ((size_t)b*NN + 2*t)*DD;     // 6 consecutive floats
#pragma unroll
    for (int d = 0; d < DD; d++) {
        atomicAdd(o0 + d,      h0*coef[d] + addc[d]);
        atomicAdd(o0 + DD + d, h1*coef[d] + addc[d]);
    }
}

// ---------------------------------------------------------------------------
extern "C" void kernel_launch(void* const* d_in, const int* in_sizes, int n_in,
                              void* d_out, int out_size)
{
    const float* x  = (const float*)d_in[0];   // (2, 3072)
    const float* W1 = (const float*)d_in[1];   // (6, 32)
    const float* b1 = (const float*)d_in[2];   // (32,)
    const float* W2 = (const float*)d_in[3];   // (64, 64)
    const float* b2 = (const float*)d_in[4];   // (64,)
    const float* W3 = (const float*)d_in[5];   // (128, 3)
    const float* b3 = (const float*)d_in[6];   // (3,)
    float* out = (float*)d_out;

    stage1<<<BB*F1, NTH>>>(x, W1, b1, out);              // 64 blocks
    stage2_fused<<<BB*F2, NTH>>>(W2, b2, W3, b3, out);   // 128 blocks
}

// round 16
// speedup vs baseline: 1.0135x; 1.0135x over previous
#include <cuda_runtime.h>

#define BB 2
#define NN 1024
#define DD 3
#define F1 32
#define F2 64
#define NTH 512
#define NB 256

// Scratch (no allocs allowed). g_h1 feature-major: [batch][feature][point]
__device__ float g_h1[BB*F1*NN];

// named barrier for a 256-thread sub-engine (ids 1 and 2; 0 is __syncthreads)
__device__ __forceinline__ void subbar(int sub) {
    asm volatile("bar.sync %0, %1;" :: "r"(sub + 1), "r"(256) : "memory");
}

// ---------------------------------------------------------------------------
// Rank engine shared state (one instance per column)
// ---------------------------------------------------------------------------
struct RankSmem {
    int   cnt[NB];
    int   cur[NB];
    float bsum[NB];
    int   E[NB+1];
    float SS[NB+1];
    float sc[NN];
    float redA[16];
    float redB[16];
};

// ---------------------------------------------------------------------------
// 2-value build, 512 threads, __syncthreads (validated R5/R13) — stage1 only
// ---------------------------------------------------------------------------
__device__ void rank_build(RankSmem* S, float c0, float c1,
                           int t, float& mn_out, float& invw_out)
{
    int lane = t & 31, w = t >> 5;

    if (t < NB) { S->cnt[t] = 0; S->bsum[t] = 0.0f; }

    float mnl = fminf(c0, c1), mxl = fmaxf(c0, c1);
#pragma unroll
    for (int o = 16; o > 0; o >>= 1) {
        mnl = fminf(mnl, __shfl_xor_sync(0xffffffffu, mnl, o));
        mxl = fmaxf(mxl, __shfl_xor_sync(0xffffffffu, mxl, o));
    }
    if (lane == 0) { S->redA[w] = mnl; S->redB[w] = mxl; }
    __syncthreads();
    if (t < 16) {
        mnl = S->redA[t]; mxl = S->redB[t];
#pragma unroll
        for (int o = 8; o > 0; o >>= 1) {
            mnl = fminf(mnl, __shfl_xor_sync(0x0000ffffu, mnl, o));
            mxl = fmaxf(mxl, __shfl_xor_sync(0x0000ffffu, mxl, o));
        }
        if (t == 0) { S->redA[0] = mnl; S->redB[0] = (float)NB / fmaxf(mxl - mnl, 1e-30f); }
    }
    __syncthreads();
    float mn = S->redA[0], invw = S->redB[0];
    mn_out = mn; invw_out = invw;

    int b0 = min(max((int)((c0 - mn) * invw), 0), NB-1);
    int b1 = min(max((int)((c1 - mn) * invw), 0), NB-1);
    atomicAdd(&S->cnt[b0], 1);  atomicAdd(&S->bsum[b0], c0);
    atomicAdd(&S->cnt[b1], 1);  atomicAdd(&S->bsum[b1], c1);
    __syncthreads();

    int v = 0; float s = 0.0f;
    int vi = 0; float si = 0.0f;
    if (t < NB) {
        v = S->cnt[t]; s = S->bsum[t];
        vi = v; si = s;
#pragma unroll
        for (int o = 1; o < 32; o <<= 1) {
            int   nv = __shfl_up_sync(0xffffffffu, vi, o);
            float ns = __shfl_up_sync(0xffffffffu, si, o);
            if (lane >= o) { vi += nv; si += ns; }
        }
        if (lane == 31) { S->redA[w] = (float)vi; S->redB[w] = si; }
    }
    __syncthreads();
    if (t < 8) {
        float v8 = S->redA[t], s8 = S->redB[t];
        float vv = v8, ss = s8;
#pragma unroll
        for (int o = 1; o < 8; o <<= 1) {
            float nv = __shfl_up_sync(0x000000ffu, vv, o);
            float ns = __shfl_up_sync(0x000000ffu, ss, o);
            if (t >= o) { vv += nv; ss += ns; }
        }
        S->redA[t] = vv - v8;
        S->redB[t] = ss - s8;
    }
    __syncthreads();
    if (t < NB) {
        int   excl  = vi - v + (int)S->redA[w];
        float exclS = si - s + S->redB[w];
        S->E[t] = excl; S->SS[t] = exclS; S->cur[t] = excl;
        if (t == NB-1) { S->E[NB] = excl + v; S->SS[NB] = exclS + s; }
    }
    __syncthreads();

    int p0 = atomicAdd(&S->cur[b0], 1);  S->sc[p0] = c0;
    int p1 = atomicAdd(&S->cur[b1], 1);  S->sc[p1] = c1;
    __syncthreads();
}

// ---------------------------------------------------------------------------
// 4-value build, 256-thread sub-engine, named barriers — stage2 only
// st in [0,256): thread owns values k=0..3 (points st + 256k)
// ---------------------------------------------------------------------------
__device__ void rank_build4(RankSmem* S, const float* c, int st, int sub,
                            float& mn_out, float& invw_out, int* bk)
{
    int lane = st & 31, w = st >> 5;     // w in 0..7

    S->cnt[st] = 0; S->bsum[st] = 0.0f;  // st covers all NB bins

    float mnl = fminf(fminf(c[0], c[1]), fminf(c[2], c[3]));
    float mxl = fmaxf(fmaxf(c[0], c[1]), fmaxf(c[2], c[3]));
#pragma unroll
    for (int o = 16; o > 0; o >>= 1) {
        mnl = fminf(mnl, __shfl_xor_sync(0xffffffffu, mnl, o));
        mxl = fmaxf(mxl, __shfl_xor_sync(0xffffffffu, mxl, o));
    }
    if (lane == 0) { S->redA[w] = mnl; S->redB[w] = mxl; }
    subbar(sub);
    if (st < 8) {
        mnl = S->redA[st]; mxl = S->redB[st];
#pragma unroll
        for (int o = 4; o > 0; o >>= 1) {
            mnl = fminf(mnl, __shfl_xor_sync(0x000000ffu, mnl, o));
            mxl = fmaxf(mxl, __shfl_xor_sync(0x000000ffu, mxl, o));
        }
        if (st == 0) { S->redA[0] = mnl; S->redB[0] = (float)NB / fmaxf(mxl - mnl, 1e-30f); }
    }
    subbar(sub);
    float mn = S->redA[0], invw = S->redB[0];
    mn_out = mn; invw_out = invw;

#pragma unroll
    for (int k = 0; k < 4; k++) {
        bk[k] = min(max((int)((c[k] - mn) * invw), 0), NB-1);
        atomicAdd(&S->cnt[bk[k]], 1);
        atomicAdd(&S->bsum[bk[k]], c[k]);
    }
    subbar(sub);

    // exclusive scan over NB bins (count + sum), 8 warps, one bin per thread
    int v = S->cnt[st];
    float s = S->bsum[st];
    int vi = v; float si = s;
#pragma unroll
    for (int o = 1; o < 32; o <<= 1) {
        int   nv = __shfl_up_sync(0xffffffffu, vi, o);
        float ns = __shfl_up_sync(0xffffffffu, si, o);
        if (lane >= o) { vi += nv; si += ns; }
    }
    if (lane == 31) { S->redA[w] = (float)vi; S->redB[w] = si; }
    subbar(sub);
    if (st < 8) {
        float v8 = S->redA[st], s8 = S->redB[st];
        float vv = v8, ss = s8;
#pragma unroll
        for (int o = 1; o < 8; o <<= 1) {
            float nv = __shfl_up_sync(0x000000ffu, vv, o);
            float ns = __shfl_up_sync(0x000000ffu, ss, o);
            if (st >= o) { vv += nv; ss += ns; }
        }
        S->redA[st] = vv - v8;
        S->redB[st] = ss - s8;
    }
    subbar(sub);
    {
        int   excl  = vi - v + (int)S->redA[w];
        float exclS = si - s + S->redB[w];
        S->E[st] = excl; S->SS[st] = exclS; S->cur[st] = excl;
        if (st == NB-1) { S->E[NB] = excl + v; S->SS[NB] = exclS + s; }
    }
    subbar(sub);

#pragma unroll
    for (int k = 0; k < 4; k++) {
        int p = atomicAdd(&S->cur[bk[k]], 1);
        S->sc[p] = c[k];
    }
    subbar(sub);
}

__device__ __forceinline__ float rank_query(const RankSmem* S, float a, float cself,
                                            float mn, float invw)
{
    const float scale = 1.0f / (float)(NN - 1);
    float q = -a;
    int qb = min(max((int)((q - mn) * invw), 0), NB-1);
    int beg = S->E[qb], end = S->E[qb+1];
    float cnt = (float)(NN - end);
    float sum = S->SS[NB] - S->SS[qb+1];
    for (int k = beg; k < end; k++) {
        float v = S->sc[k];
        if (v > q) { cnt += 1.0f; sum += v; }
    }
    float self = fmaxf(a + cself, 0.0f);
    return (a * cnt + sum - self) * scale;
}

// ---------------------------------------------------------------------------
// Stage 1 (identical to R13): one block per (batch, feature f of 32).
// Thread t owns points (t, t+512). Writes h1 column. Also zeroes out.
// ---------------------------------------------------------------------------
__global__ __launch_bounds__(NTH) void stage1(
    const float* __restrict__ x,
    const float* __restrict__ W1,
    const float* __restrict__ b1,
    float* __restrict__ out)
{
    __shared__ RankSmem S;

    int t = threadIdx.x;

    int zi = blockIdx.x * NTH + t;
    if (zi < BB*NN*DD) out[zi] = 0.0f;

    int b = blockIdx.x >> 5;
    int f = blockIdx.x & 31;

    float w0 = W1[0*F1+f], w1 = W1[1*F1+f], w2 = W1[2*F1+f];
    float w3 = W1[3*F1+f], w4 = W1[4*F1+f], w5 = W1[5*F1+f];
    float bias = b1[f];
    const float* xb = x + b*NN*DD;

    float a0, a1, c0, c1;
    {
        float x0 = xb[3*t+0], x1 = xb[3*t+1], x2 = xb[3*t+2];
        a0 = x0*w0 + x1*w1 + x2*w2 + bias;
        c0 = x0*w3 + x1*w4 + x2*w5;
        int p = t + 512;
        x0 = xb[3*p+0]; x1 = xb[3*p+1]; x2 = xb[3*p+2];
        a1 = x0*w0 + x1*w1 + x2*w2 + bias;
        c1 = x0*w3 + x1*w4 + x2*w5;
    }

    float mn, invw;
    rank_build(&S, c0, c1, t, mn, invw);

    float* hout = g_h1 + (b*F1 + f)*NN;
    hout[t]       = rank_query(&S, a0, c0, mn, invw);
    hout[t + 512] = rank_query(&S, a1, c1, mn, invw);
}

// ---------------------------------------------------------------------------
// Stage 2: TWO columns per block. warps 0-7 -> column 2k, warps 8-15 -> 2k+1.
// Sub-engines use named barriers; each thread owns 4 points (st + 256k),
// lane-consecutive (preserves R13's atomic sector behavior).
//   out[i,d] += h2[i]*(Wt[f2,d] - Wb[f2,d]*inv) + Hsum*Wb[f2,d]*inv + b3[d]/F2
// ---------------------------------------------------------------------------
__global__ __launch_bounds__(NTH) void stage2_fused(
    const float* __restrict__ W2,
    const float* __restrict__ b2,
    const float* __restrict__ W3,
    const float* __restrict__ b3,
    float* __restrict__ out)
{
    __shared__ RankSmem S[2];
    __shared__ float wt[2][F1], wb[2][F1];

    int t = threadIdx.x;
    int sub = t >> 8;            // 0 or 1
    int st  = t & 255;
    int b   = blockIdx.x >> 5;                 // 32 blocks per batch
    int f2  = ((blockIdx.x & 31) << 1) | sub;  // column of this sub-engine

    if (st < F1) {
        wt[sub][st] = W2[st*F2 + f2];
        wb[sub][st] = W2[(F1 + st)*F2 + f2];
    }
    float bias = b2[f2];
    subbar(sub);

    // projection: 4 points (st + 256k), lane-consecutive loads
    const float* h1b = g_h1 + b*F1*NN;
    float a[4], c[4];
#pragma unroll
    for (int k = 0; k < 4; k++) { a[k] = bias; c[k] = 0.0f; }
#pragma unroll 8
    for (int f = 0; f < F1; f++) {
        float wtf = wt[sub][f], wbf = wb[sub][f];
#pragma unroll
        for (int k = 0; k < 4; k++) {
            float hv = __ldg(&h1b[f*NN + st + 256*k]);   // cross-kernel: safe
            a[k] += hv * wtf;
            c[k] += hv * wbf;
        }
    }

    float mn, invw;
    int bk[4];
    rank_build4(&S[sub], c, st, sub, mn, invw, bk);

    float h[4];
#pragma unroll
    for (int k = 0; k < 4; k++)
        h[k] = rank_query(&S[sub], a[k], c[k], mn, invw);

    // sub-engine reduce: Hsum = sum_i h2[i]
    float hloc = (h[0] + h[1]) + (h[2] + h[3]);
    int lane = st & 31, w = st >> 5;
#pragma unroll
    for (int o = 16; o > 0; o >>= 1)
        hloc += __shfl_xor_sync(0xffffffffu, hloc, o);
    if (lane == 0) S[sub].redA[w] = hloc;
    subbar(sub);
    if (st < 8) {
        float v = S[sub].redA[st];
#pragma unroll
        for (int o = 4; o > 0; o >>= 1)
            v += __shfl_xor_sync(0x000000ffu, v, o);
        if (st == 0) S[sub].redA[0] = v;
    }
    subbar(sub);
    float Hsum = S[sub].redA[0];

    // direct output commit (F2=64 columns contribute per output point)
    const float inv = 1.0f / (float)(NN - 1);
    float coef[DD], addc[DD];
#pragma unroll
    for (int d = 0; d < DD; d++) {
        float wtd = W3[f2*DD + d];
        float wbd = W3[(F2 + f2)*DD + d];
        coef[d] = wtd - wbd*inv;
        addc[d] = Hsum*wbd*inv + b3[d]*(1.0f/(float)F2);
    }
#pragma unroll
    for (int k = 0; k < 4; k++) {
        float* o0 = out + ((size_t)b*NN + st + 256*k)*DD;
#pragma unroll
        for (int d = 0; d < DD; d++)
            atomicAdd(o0 + d, h[k]*coef[d] + addc[d]);
    }
}

// ---------------------------------------------------------------------------
extern "C" void kernel_launch(void* const* d_in, const int* in_sizes, int n_in,
                              void* d_out, int out_size)
{
    const float* x  = (const float*)d_in[0];   // (2, 3072)
    const float* W1 = (const float*)d_in[1];   // (6, 32)
    const float* b1 = (const float*)d_in[2];   // (32,)
    const float* W2 = (const float*)d_in[3];   // (64, 64)
    const float* b2 = (const float*)d_in[4];   // (64,)
    const float* W3 = (const float*)d_in[5];   // (128, 3)
    const float* b3 = (const float*)d_in[6];   // (3,)
    float* out = (float*)d_out;

    stage1<<<BB*F1, NTH>>>(x, W1, b1, out);                // 64 blocks
    stage2_fused<<<BB*(F2/2), NTH>>>(W2, b2, W3, b3, out); // 64 blocks, 2 cols each
}

// round 17
// speedup vs baseline: 1.2937x; 1.2765x over previous
#include <cuda_runtime.h>

#define BB 2
#define NN 1024
#define DD 3
#define F1 32
#define F2 64
#define NTH 512
#define NB 256

// Scratch (no allocs allowed). g_h1 feature-major: [batch][feature][point]
__device__ float g_h1[BB*F1*NN];

// ---------------------------------------------------------------------------
// Rank-query engine (validated R5/R13): cnt/sum of {c_j > q} via 256-bin
// counting histogram + bucket scan. Ties contribute a + c == 0 -> free.
// ---------------------------------------------------------------------------
struct RankSmem {
    int   cnt[NB];
    int   cur[NB];
    float bsum[NB];
    int   E[NB+1];
    float SS[NB+1];
    float sc[NN];
    float redA[16];
    float redB[16];
};

__device__ void rank_build(RankSmem* S, float c0, float c1,
                           int t, float& mn_out, float& invw_out)
{
    int lane = t & 31, w = t >> 5;

    if (t < NB) { S->cnt[t] = 0; S->bsum[t] = 0.0f; }

    // block min/max of c
    float mnl = fminf(c0, c1), mxl = fmaxf(c0, c1);
#pragma unroll
    for (int o = 16; o > 0; o >>= 1) {
        mnl = fminf(mnl, __shfl_xor_sync(0xffffffffu, mnl, o));
        mxl = fmaxf(mxl, __shfl_xor_sync(0xffffffffu, mxl, o));
    }
    if (lane == 0) { S->redA[w] = mnl; S->redB[w] = mxl; }
    __syncthreads();
    if (t < 16) {
        mnl = S->redA[t]; mxl = S->redB[t];
#pragma unroll
        for (int o = 8; o > 0; o >>= 1) {
            mnl = fminf(mnl, __shfl_xor_sync(0x0000ffffu, mnl, o));
            mxl = fmaxf(mxl, __shfl_xor_sync(0x0000ffffu, mxl, o));
        }
        if (t == 0) { S->redA[0] = mnl; S->redB[0] = (float)NB / fmaxf(mxl - mnl, 1e-30f); }
    }
    __syncthreads();
    float mn = S->redA[0], invw = S->redB[0];
    mn_out = mn; invw_out = invw;

    int b0 = min(max((int)((c0 - mn) * invw), 0), NB-1);
    int b1 = min(max((int)((c1 - mn) * invw), 0), NB-1);
    atomicAdd(&S->cnt[b0], 1);  atomicAdd(&S->bsum[b0], c0);
    atomicAdd(&S->cnt[b1], 1);  atomicAdd(&S->bsum[b1], c1);
    __syncthreads();

    // exclusive scan over NB bins (count + sum), warps 0..7
    int v = 0; float s = 0.0f;
    int vi = 0; float si = 0.0f;
    if (t < NB) {
        v = S->cnt[t]; s = S->bsum[t];
        vi = v; si = s;
#pragma unroll
        for (int o = 1; o < 32; o <<= 1) {
            int   nv = __shfl_up_sync(0xffffffffu, vi, o);
            float ns = __shfl_up_sync(0xffffffffu, si, o);
            if (lane >= o) { vi += nv; si += ns; }
        }
        if (lane == 31) { S->redA[w] = (float)vi; S->redB[w] = si; }
    }
    __syncthreads();
    if (t < 8) {
        float v8 = S->redA[t], s8 = S->redB[t];
        float vv = v8, ss = s8;
#pragma unroll
        for (int o = 1; o < 8; o <<= 1) {
            float nv = __shfl_up_sync(0x000000ffu, vv, o);
            float ns = __shfl_up_sync(0x000000ffu, ss, o);
            if (t >= o) { vv += nv; ss += ns; }
        }
        S->redA[t] = vv - v8;
        S->redB[t] = ss - s8;
    }
    __syncthreads();
    if (t < NB) {
        int   excl  = vi - v + (int)S->redA[w];
        float exclS = si - s + S->redB[w];
        S->E[t] = excl; S->SS[t] = exclS; S->cur[t] = excl;
        if (t == NB-1) { S->E[NB] = excl + v; S->SS[NB] = exclS + s; }
    }
    __syncthreads();

    int p0 = atomicAdd(&S->cur[b0], 1);  S->sc[p0] = c0;
    int p1 = atomicAdd(&S->cur[b1], 1);  S->sc[p1] = c1;
    __syncthreads();
}

__device__ __forceinline__ float rank_query(const RankSmem* S, float a, float cself,
                                            float mn, float invw)
{
    const float scale = 1.0f / (float)(NN - 1);
    float q = -a;
    int qb = min(max((int)((q - mn) * invw), 0), NB-1);
    int beg = S->E[qb], end = S->E[qb+1];
    float cnt = (float)(NN - end);
    float sum = S->SS[NB] - S->SS[qb+1];
    for (int k = beg; k < end; k++) {
        float v = S->sc[k];
        if (v > q) { cnt += 1.0f; sum += v; }
    }
    float self = fmaxf(a + cself, 0.0f);
    return (a * cnt + sum - self) * scale;
}

// ---------------------------------------------------------------------------
// Stage 1 (identical to R13): one block per (batch, feature f of 32).
// Thread t owns points (t, t+512). Writes h1 column. Also zeroes out.
// ---------------------------------------------------------------------------
__global__ __launch_bounds__(NTH) void stage1(
    const float* __restrict__ x,
    const float* __restrict__ W1,
    const float* __restrict__ b1,
    float* __restrict__ out)
{
    __shared__ RankSmem S;

    int t = threadIdx.x;

    // zero output (64 blocks x 512 threads >= 6144 elements)
    int zi = blockIdx.x * NTH + t;
    if (zi < BB*NN*DD) out[zi] = 0.0f;

    int b = blockIdx.x >> 5;
    int f = blockIdx.x & 31;

    float w0 = W1[0*F1+f], w1 = W1[1*F1+f], w2 = W1[2*F1+f];
    float w3 = W1[3*F1+f], w4 = W1[4*F1+f], w5 = W1[5*F1+f];
    float bias = b1[f];
    const float* xb = x + b*NN*DD;

    float a0, a1, c0, c1;
    {
        float x0 = xb[3*t+0], x1 = xb[3*t+1], x2 = xb[3*t+2];
        a0 = x0*w0 + x1*w1 + x2*w2 + bias;
        c0 = x0*w3 + x1*w4 + x2*w5;
        int p = t + 512;
        x0 = xb[3*p+0]; x1 = xb[3*p+1]; x2 = xb[3*p+2];
        a1 = x0*w0 + x1*w1 + x2*w2 + bias;
        c1 = x0*w3 + x1*w4 + x2*w5;
    }

    float mn, invw;
    rank_build(&S, c0, c1, t, mn, invw);

    float* hout = g_h1 + (b*F1 + f)*NN;
    hout[t]       = rank_query(&S, a0, c0, mn, invw);
    hout[t + 512] = rank_query(&S, a1, c1, mn, invw);
}

// ---------------------------------------------------------------------------
// Stage 2 (R13 structure; MLP-widened projection): one block per (batch, f2).
// Thread t owns points (t, t+512) — the validated mapping. launch_bounds(,1)
// removes the occupancy register cap (grid 128 = 1 block/SM anyway), and the
// projection issues 16 loads per batch before consuming them.
//   out[i,d] += h2[i]*(Wt[f2,d] - Wb[f2,d]*inv) + Hsum*Wb[f2,d]*inv + b3[d]/F2
// ---------------------------------------------------------------------------
__global__ __launch_bounds__(NTH, 1) void stage2_fused(
    const float* __restrict__ W2,
    const float* __restrict__ b2,
    const float* __restrict__ W3,
    const float* __restrict__ b3,
    float* __restrict__ out)
{
    __shared__ RankSmem S;
    __shared__ float wt[F1], wb[F1];

    int t = threadIdx.x;
    int b = blockIdx.x >> 6;
    int f2 = blockIdx.x & 63;

    if (t < F1) {
        wt[t] = W2[t*F2 + f2];
        wb[t] = W2[(F1 + t)*F2 + f2];
    }
    float bias = b2[f2];
    __syncthreads();

    // projection with explicit load batching: 16 outstanding LDG per group
    const float* h1b = g_h1 + b*F1*NN;
    float a0 = bias, c0 = 0.0f, a1 = bias, c1 = 0.0f;
#pragma unroll
    for (int fo = 0; fo < F1; fo += 8) {
        float hv0[8], hv1[8];
#pragma unroll
        for (int k = 0; k < 8; k++) {
            hv0[k] = __ldg(&h1b[(fo+k)*NN + t]);        // cross-kernel: safe
            hv1[k] = __ldg(&h1b[(fo+k)*NN + t + 512]);
        }
#pragma unroll
        for (int k = 0; k < 8; k++) {
            a0 += hv0[k] * wt[fo+k];  c0 += hv0[k] * wb[fo+k];
            a1 += hv1[k] * wt[fo+k];  c1 += hv1[k] * wb[fo+k];
        }
    }

    float mn, invw;
    rank_build(&S, c0, c1, t, mn, invw);

    float h0 = rank_query(&S, a0, c0, mn, invw);
    float h1 = rank_query(&S, a1, c1, mn, invw);

    // block-reduce Hsum = sum_i h2[i]
    float hloc = h0 + h1;
    __syncthreads();
    int lane = t & 31, w = t >> 5;
#pragma unroll
    for (int o = 16; o > 0; o >>= 1)
        hloc += __shfl_xor_sync(0xffffffffu, hloc, o);
    if (lane == 0) S.redA[w] = hloc;
    __syncthreads();
    if (t < 16) {
        float v = S.redA[t];
#pragma unroll
        for (int o = 8; o > 0; o >>= 1)
            v += __shfl_xor_sync(0x0000ffffu, v, o);
        if (t == 0) S.redA[0] = v;
    }
    __syncthreads();
    float Hsum = S.redA[0];

    // direct output commit (F2=64 blocks contribute per output point)
    const float inv = 1.0f / (float)(NN - 1);
    float coef[DD], addc[DD];
#pragma unroll
    for (int d = 0; d < DD; d++) {
        float wtd = W3[f2*DD + d];
        float wbd = W3[(F2 + f2)*DD + d];
        coef[d] = wtd - wbd*inv;
        addc[d] = Hsum*wbd*inv + b3[d]*(1.0f/(float)F2);
    }
    float* o0 = out + ((size_t)b*NN + t)*DD;
    float* o1 = out + ((size_t)b*NN + t + 512)*DD;
#pragma unroll
    for (int d = 0; d < DD; d++) {
        atomicAdd(o0 + d, h0*coef[d] + addc[d]);
        atomicAdd(o1 + d, h1*coef[d] + addc[d]);
    }
}

// ---------------------------------------------------------------------------
extern "C" void kernel_launch(void* const* d_in, const int* in_sizes, int n_in,
                              void* d_out, int out_size)
{
    const float* x  = (const float*)d_in[0];   // (2, 3072)
    const float* W1 = (const float*)d_in[1];   // (6, 32)
    const float* b1 = (const float*)d_in[2];   // (32,)
    const float* W2 = (const float*)d_in[3];   // (64, 64)
    const float* b2 = (const float*)d_in[4];   // (64,)
    const float* W3 = (const float*)d_in[5];   // (128, 3)
    const float* b3 = (const float*)d_in[6];   // (3,)
    float* out = (float*)d_out;

    stage1<<<BB*F1, NTH>>>(x, W1, b1, out);              // 64 blocks
    stage2_fused<<<BB*F2, NTH>>>(W2, b2, W3, b3, out);   // 128 blocks
}